// round 1
// baseline (speedup 1.0000x reference)
#include <cuda_runtime.h>
#include <math.h>

#define EPSF 1e-8f
#define LOG2E 1.4426950408889634f

constexpr int Bn  = 4096;
constexpr int Ln  = 1024;
constexpr int Kc  = 4;
constexpr int NIT = 5;
constexpr int TPB = 256;
constexpr int LPT = Ln / TPB;   // 4 positions per thread
constexpr int NW  = TPB / 32;   // 8 warps

__device__ __forceinline__ float warp_sum(float v) {
#pragma unroll
    for (int o = 16; o; o >>= 1) v += __shfl_xor_sync(0xffffffffu, v, o);
    return v;
}

__device__ __forceinline__ float ex2f(float x) {
    float r;
    asm("ex2.approx.ftz.f32 %0, %1;" : "=f"(r) : "f"(x));
    return r;
}

__global__ __launch_bounds__(TPB) void em_kernel(
    const float* __restrict__ windows,        // [B, L]
    const float* __restrict__ noise,          // [B, K]
    const float* __restrict__ init_centers,   // [K]
    const float* __restrict__ init_scales,    // [K]
    const float* __restrict__ init_weights,   // [K]
    const float* __restrict__ prior_p_param,  // [1]
    const float* __restrict__ mixw,           // [1, L]
    const float* __restrict__ blend,          // [1]
    float* __restrict__ out)                  // g [B,L,K] ++ p [B,K] ++ a [B,K] ++ b [B,K]
{
    __shared__ float sh_t[Ln];       // centered row
    __shared__ float sh_w[Ln];       // exp(mix_weights)
    __shared__ float red[NW * 12];
    __shared__ float tot[12];

    const int row  = blockIdx.x;
    const int tid  = threadIdx.x;
    const int lane = tid & 31;
    const int wid  = tid >> 5;
    const float* __restrict__ x = windows + (size_t)row * Ln;

    // ---- pass 1: load row, row-sum; also fill per-position weights ----
    float xs[LPT];
    float s = 0.f;
#pragma unroll
    for (int i = 0; i < LPT; i++) {
        int l = tid + i * TPB;
        xs[i] = x[l];
        s += xs[i];
        sh_w[l] = __expf(mixw[l]);
    }
    s = warp_sum(s);
    if (lane == 0) red[wid] = s;
    __syncthreads();
    float mean = 0.f;
#pragma unroll
    for (int w = 0; w < NW; w++) mean += red[w];
    mean *= (1.0f / Ln);
    __syncthreads();   // red about to be reused

    // ---- pass 2: center, store to smem, sum of squares (ddof=1 var) ----
    float ss = 0.f;
#pragma unroll
    for (int i = 0; i < LPT; i++) {
        int l = tid + i * TPB;
        float t = xs[i] - mean;
        sh_t[l] = t;
        ss += t * t;
    }
    ss = warp_sum(ss);
    if (lane == 0) red[wid] = ss;
    __syncthreads();
    float var = 0.f;
#pragma unroll
    for (int w = 0; w < NW; w++) var += red[w];
    var *= (1.0f / (Ln - 1));

    const float stdv      = sqrtf(var);
    const float prior_var = var;
    const float prior_p   = 1.f / (1.f + __expf(-prior_p_param[0]));
    const float blender   = 1.f / (1.f + __expf(-blend[0]));
    const float omb       = 1.f - blender;

    // ---- initial parameters (in mean-centered coordinates: alpha = a - mean) ----
    float alpha[Kc], ib[Kc], lw2[Kc], c2[Kc], pk[Kc], bk[Kc];
#pragma unroll
    for (int k = 0; k < Kc; k++) {
        alpha[k] = (init_centers[k] + noise[(size_t)row * Kc + k] * 0.01f) * stdv;
        bk[k]    = fabsf(init_scales[k]) * stdv;
        pk[k]    = init_weights[k];
        ib[k]    = __fdividef(1.f, bk[k] + EPSF);
        lw2[k]   = __logf((pk[k] + EPSF) * ib[k]) * LOG2E;
        c2[k]    = -0.5f * ib[k] * ib[k] * LOG2E;
    }

    // ---- EM iterations ----
    for (int it = 0; it < NIT; it++) {
        float T0[Kc] = {0.f, 0.f, 0.f, 0.f};
        float T1[Kc] = {0.f, 0.f, 0.f, 0.f};
        float T2[Kc] = {0.f, 0.f, 0.f, 0.f};
        const bool last = (it == NIT - 1);

#pragma unroll
        for (int i = 0; i < LPT; i++) {
            int l = tid + i * TPB;
            float t  = sh_t[l];
            float lm[Kc], e[Kc];
#pragma unroll
            for (int k = 0; k < Kc; k++) {
                float d = t - alpha[k];
                lm[k] = fmaf(c2[k] * d, d, lw2[k]);   // log2-domain mixture logit
            }
            float m = fmaxf(fmaxf(lm[0], lm[1]), fmaxf(lm[2], lm[3]));
            float ssum = 0.f;
#pragma unroll
            for (int k = 0; k < Kc; k++) { e[k] = ex2f(lm[k] - m); ssum += e[k]; }
            float rs = __fdividef(1.f, ssum);

            if (last) {
                float4 g4 = make_float4(e[0] * rs, e[1] * rs, e[2] * rs, e[3] * rs);
                *reinterpret_cast<float4*>(out + ((size_t)row * Ln + l) * Kc) = g4;
            }

            float ws = sh_w[l] * rs;
#pragma unroll
            for (int k = 0; k < Kc; k++) {
                float gw  = e[k] * ws;
                float gwt = gw * t;
                T0[k] += gw;
                T1[k] += gwt;
                T2[k]  = fmaf(gwt, t, T2[k]);
            }
        }

        // ---- block-reduce the 12 moments ----
        __syncthreads();   // previous-iteration readers of red/tot are done
#pragma unroll
        for (int k = 0; k < Kc; k++) {
            float v0 = warp_sum(T0[k]);
            float v1 = warp_sum(T1[k]);
            float v2 = warp_sum(T2[k]);
            if (lane == 0) {
                red[wid * 12 + k]     = v0;
                red[wid * 12 + 4 + k] = v1;
                red[wid * 12 + 8 + k] = v2;
            }
        }
        __syncthreads();
        if (tid < 12) {
            float v = 0.f;
#pragma unroll
            for (int w = 0; w < NW; w++) v += red[w * 12 + tid];
            tot[tid] = v;
        }
        __syncthreads();

        // ---- m-step (computed redundantly on every thread; all-scalar) ----
        float psum = 0.f;
        float S0[Kc], S1[Kc], S2[Kc], sg[Kc];
#pragma unroll
        for (int k = 0; k < Kc; k++) {
            S0[k] = tot[k];
            S1[k] = tot[4 + k];
            S2[k] = tot[8 + k];
            sg[k] = fmaxf(S0[k], EPSF);
            pk[k] = sg[k] + prior_p;
            psum += pk[k];
        }
        float rp = __fdividef(1.f, psum);
#pragma unroll
        for (int k = 0; k < Kc; k++) {
            pk[k] *= rp;
            float rsg    = __fdividef(1.f, sg[k]);
            float data_a = (S1[k] + mean * S0[k]) * rsg;
            float a      = data_a * blender + mean * omb;
            float al     = a - mean;
            float dv     = (S2[k] - 2.f * al * S1[k] + al * al * S0[k]) * rsg;
            bk[k]    = sqrtf(dv * blender + prior_var * omb + EPSF);
            alpha[k] = al;
            ib[k]    = __fdividef(1.f, bk[k] + EPSF);
            lw2[k]   = __logf((pk[k] + EPSF) * ib[k]) * LOG2E;
            c2[k]    = -0.5f * ib[k] * ib[k] * LOG2E;
        }
    }

    // ---- tail outputs: p, a, b ([B,K] each, after g) ----
    if (tid < Kc) {
        size_t base = (size_t)Bn * Ln * Kc;
        out[base + (size_t)row * Kc + tid]                        = pk[tid];
        out[base + (size_t)Bn * Kc + (size_t)row * Kc + tid]      = alpha[tid] + mean;
        out[base + 2 * (size_t)Bn * Kc + (size_t)row * Kc + tid]  = bk[tid];
    }
}

extern "C" void kernel_launch(void* const* d_in, const int* in_sizes, int n_in,
                              void* d_out, int out_size) {
    (void)in_sizes; (void)n_in; (void)out_size;
    const float* windows      = (const float*)d_in[0];
    const float* noise        = (const float*)d_in[1];
    const float* init_centers = (const float*)d_in[2];
    const float* init_scales  = (const float*)d_in[3];
    const float* init_weights = (const float*)d_in[4];
    const float* prior_p      = (const float*)d_in[5];
    const float* mix_weights  = (const float*)d_in[6];
    const float* blend        = (const float*)d_in[7];
    float* out = (float*)d_out;

    em_kernel<<<Bn, TPB>>>(windows, noise, init_centers, init_scales, init_weights,
                           prior_p, mix_weights, blend, out);
}

// round 2
// speedup vs baseline: 1.6930x; 1.6930x over previous
#include <cuda_runtime.h>
#include <math.h>

#define EPSF 1e-8f
#define LOG2E 1.4426950408889634f
#define NHALF_LOG2E (-0.72134752044448170f)   // -0.5 * log2(e)

constexpr int Bn  = 4096;
constexpr int Ln  = 1024;
constexpr int Kc  = 4;
constexpr int NIT = 5;
constexpr int TPB = 256;
constexpr int LPT = 4;          // positions per thread (contiguous)
constexpr int NW  = TPB / 32;

__device__ __forceinline__ float ex2f(float x) {
    float r; asm("ex2.approx.ftz.f32 %0, %1;" : "=f"(r) : "f"(x)); return r;
}
__device__ __forceinline__ float rcpf(float x) {
    float r; asm("rcp.approx.ftz.f32 %0, %1;" : "=f"(r) : "f"(x)); return r;
}
__device__ __forceinline__ float warp_sum(float v) {
#pragma unroll
    for (int o = 16; o; o >>= 1) v += __shfl_xor_sync(0xffffffffu, v, o);
    return v;
}

struct Smem {
    float red[TPB][13];   // per-thread partials, stride 13 => conflict-free
    float part[12][8];    // per-chunk partials (12 moments x 8 chunks of 32 threads)
    float spar[12];       // qa[4], qb[4], qc[4]
    float sout[12];       // p[4], a[4], b[4]
    float rtmp[NW];
};

// ---- e-step over this thread's 4 positions; accumulates 12 moments ----
template <bool STORE>
__device__ __forceinline__ void estep(const float* __restrict__ t,
                                      const float* __restrict__ t2,
                                      const float* __restrict__ w,
                                      const Smem* sm,
                                      float* __restrict__ acc,
                                      float4* __restrict__ gout) {
    float qa[Kc], qb[Kc], qc[Kc];
#pragma unroll
    for (int k = 0; k < Kc; k++) {
        qa[k] = sm->spar[k];
        qb[k] = sm->spar[4 + k];
        qc[k] = sm->spar[8 + k];
    }
#pragma unroll
    for (int i = 0; i < LPT; i++) {
        float lm[Kc], e[Kc];
#pragma unroll
        for (int k = 0; k < Kc; k++) {
            lm[k] = fmaf(qa[k], t2[i], qc[k]);
            lm[k] = fmaf(qb[k], t[i], lm[k]);
        }
        float ssum = 0.f;
#pragma unroll
        for (int k = 0; k < Kc; k++) { e[k] = ex2f(lm[k]); ssum += e[k]; }
        float rs = rcpf(ssum);
        if (STORE) {
            gout[i] = make_float4(e[0] * rs, e[1] * rs, e[2] * rs, e[3] * rs);
        }
        float ws = w[i] * rs;
#pragma unroll
        for (int k = 0; k < Kc; k++) {
            float f = e[k] * ws;
            acc[k]     += f;
            acc[4 + k]  = fmaf(f, t[i], acc[4 + k]);
            acc[8 + k]  = fmaf(f, t2[i], acc[8 + k]);
        }
    }
}

// ---- cross-block reduction of the 12 moments + m-step on warp 0 ----
__device__ __forceinline__ void reduce_and_mstep(
    Smem* sm, const float* __restrict__ acc,
    int tid, int lane, int wid,
    float mean, float prior_var, float prior_p, float blender, float omb) {

#pragma unroll
    for (int m = 0; m < 12; m++) sm->red[tid][m] = acc[m];
    __syncthreads();

    if (tid < 96) {
        int m = tid % 12, c = tid / 12;
        float v = 0.f;
#pragma unroll
        for (int i = 0; i < 32; i++) v += sm->red[c * 32 + i][m];
        sm->part[m][c] = v;
    }
    __syncthreads();

    if (wid == 0) {
        int k = lane & 3;
        float S0 = 0.f, S1 = 0.f, S2 = 0.f;
#pragma unroll
        for (int c = 0; c < 8; c++) {
            S0 += sm->part[k][c];
            S1 += sm->part[4 + k][c];
            S2 += sm->part[8 + k][c];
        }
        float sg = fmaxf(S0, EPSF);
        float pk = sg + prior_p;
        float psum = pk;
        psum += __shfl_xor_sync(0xffffffffu, psum, 1);
        psum += __shfl_xor_sync(0xffffffffu, psum, 2);
        float pkn = pk * rcpf(psum);
        float rsg = rcpf(sg);
        float al  = blender * S1 * rsg;                               // a - mean
        float dv  = fmaf(al, fmaf(al, S0, -2.f * S1), S2) * rsg;      // weighted var
        float bb  = sqrtf(fmaf(dv, blender, fmaf(prior_var, omb, EPSF)));
        float ib  = rcpf(bb + EPSF);
        float qa  = NHALF_LOG2E * ib * ib;
        float qb  = -2.f * qa * al;
        float qc  = fmaf(qa * al, al, __log2f((pkn + EPSF) * ib));
        if (lane < 4) {
            sm->spar[k]     = qa;
            sm->spar[4 + k] = qb;
            sm->spar[8 + k] = qc;
            sm->sout[k]     = pkn;
            sm->sout[4 + k] = al + mean;
            sm->sout[8 + k] = bb;
        }
    }
    __syncthreads();
}

__global__ __launch_bounds__(TPB) void em_kernel(
    const float* __restrict__ windows,        // [B, L]
    const float* __restrict__ noise,          // [B, K]
    const float* __restrict__ init_centers,   // [K]
    const float* __restrict__ init_scales,    // [K]
    const float* __restrict__ init_weights,   // [K]
    const float* __restrict__ prior_p_param,  // [1]
    const float* __restrict__ mixw,           // [1, L]
    const float* __restrict__ blend,          // [1]
    float* __restrict__ out)                  // g [B,L,K] ++ p ++ a ++ b
{
    __shared__ Smem sm;

    const int row  = blockIdx.x;
    const int tid  = threadIdx.x;
    const int lane = tid & 31;
    const int wid  = tid >> 5;

    // ---- vectorized load: thread owns positions l = tid*4 .. tid*4+3 ----
    const float4 x4  = reinterpret_cast<const float4*>(windows + (size_t)row * Ln)[tid];
    const float4 mw4 = reinterpret_cast<const float4*>(mixw)[tid];
    float traw[LPT] = {x4.x, x4.y, x4.z, x4.w};
    float w[LPT]    = {__expf(mw4.x), __expf(mw4.y), __expf(mw4.z), __expf(mw4.w)};

    // ---- row mean ----
    float s = traw[0] + traw[1] + traw[2] + traw[3];
    s = warp_sum(s);
    if (lane == 0) sm.rtmp[wid] = s;
    __syncthreads();
    float mean = 0.f;
#pragma unroll
    for (int i = 0; i < NW; i++) mean += sm.rtmp[i];
    mean *= (1.0f / Ln);
    __syncthreads();

    // ---- center + row var (ddof=1) ----
    float t[LPT], t2[LPT];
    float ss = 0.f;
#pragma unroll
    for (int i = 0; i < LPT; i++) {
        t[i]  = traw[i] - mean;
        t2[i] = t[i] * t[i];
        ss   += t2[i];
    }
    ss = warp_sum(ss);
    if (lane == 0) sm.rtmp[wid] = ss;
    __syncthreads();
    float var = 0.f;
#pragma unroll
    for (int i = 0; i < NW; i++) var += sm.rtmp[i];
    var *= (1.0f / (Ln - 1));

    const float prior_var = var;

    // ---- scalar hyper-params + initial component params (warp 0 only) ----
    float prior_p = 0.f, blender = 0.f, omb = 0.f;
    if (wid == 0) {
        const float stdv = sqrtf(var);
        prior_p = rcpf(1.f + __expf(-prior_p_param[0]));
        blender = rcpf(1.f + __expf(-blend[0]));
        omb     = 1.f - blender;

        int k = lane & 3;
        float al = (init_centers[k] + noise[(size_t)row * Kc + k] * 0.01f) * stdv;
        float bb = fabsf(init_scales[k]) * stdv;
        float p0 = init_weights[k];
        float ib = rcpf(bb + EPSF);
        float qa = NHALF_LOG2E * ib * ib;
        float qb = -2.f * qa * al;
        float qc = fmaf(qa * al, al, __log2f((p0 + EPSF) * ib));
        if (lane < 4) {
            sm.spar[k]     = qa;
            sm.spar[4 + k] = qb;
            sm.spar[8 + k] = qc;
        }
    }
    __syncthreads();

    float4* gout = reinterpret_cast<float4*>(out) + (size_t)row * Ln + (size_t)tid * LPT;

    // ---- iterations 0..3 (no g store) ----
#pragma unroll 1
    for (int it = 0; it < NIT - 1; ++it) {
        float acc[12] = {0.f, 0.f, 0.f, 0.f, 0.f, 0.f, 0.f, 0.f, 0.f, 0.f, 0.f, 0.f};
        estep<false>(t, t2, w, &sm, acc, gout);
        reduce_and_mstep(&sm, acc, tid, lane, wid, mean, prior_var, prior_p, blender, omb);
    }
    // ---- final iteration: store g, then final m-step for p,a,b ----
    {
        float acc[12] = {0.f, 0.f, 0.f, 0.f, 0.f, 0.f, 0.f, 0.f, 0.f, 0.f, 0.f, 0.f};
        estep<true>(t, t2, w, &sm, acc, gout);
        reduce_and_mstep(&sm, acc, tid, lane, wid, mean, prior_var, prior_p, blender, omb);
    }

    // ---- tail outputs: p, a, b ----
    if (tid < Kc) {
        size_t base = (size_t)Bn * Ln * Kc;
        out[base + (size_t)row * Kc + tid]                       = sm.sout[tid];
        out[base + (size_t)Bn * Kc + (size_t)row * Kc + tid]     = sm.sout[4 + tid];
        out[base + 2 * (size_t)Bn * Kc + (size_t)row * Kc + tid] = sm.sout[8 + tid];
    }
}

extern "C" void kernel_launch(void* const* d_in, const int* in_sizes, int n_in,
                              void* d_out, int out_size) {
    (void)in_sizes; (void)n_in; (void)out_size;
    em_kernel<<<Bn, TPB>>>((const float*)d_in[0], (const float*)d_in[1],
                           (const float*)d_in[2], (const float*)d_in[3],
                           (const float*)d_in[4], (const float*)d_in[5],
                           (const float*)d_in[6], (const float*)d_in[7],
                           (float*)d_out);
}

// round 3
// speedup vs baseline: 1.9300x; 1.1400x over previous
#include <cuda_runtime.h>
#include <math.h>

#define EPSF 1e-8f
#define NHALF_LOG2E (-0.72134752044448170f)   // -0.5 * log2(e)

constexpr int Bn  = 4096;
constexpr int Ln  = 1024;
constexpr int Kc  = 4;
constexpr int NIT = 5;
constexpr int TPB = 256;
constexpr int RPB = TPB / 32;   // 8 rows (warps) per CTA
constexpr int PPL = Ln / 32;    // 32 positions per lane

__device__ __forceinline__ float ex2f(float x) {
    float r; asm("ex2.approx.ftz.f32 %0, %1;" : "=f"(r) : "f"(x)); return r;
}
__device__ __forceinline__ float rcpf(float x) {
    float r; asm("rcp.approx.ftz.f32 %0, %1;" : "=f"(r) : "f"(x)); return r;
}
__device__ __forceinline__ float warp_sum(float v) {
#pragma unroll
    for (int o = 16; o; o >>= 1) v += __shfl_xor_sync(0xffffffffu, v, o);
    return v;
}

__global__ __launch_bounds__(TPB, 2) void em_kernel(
    const float* __restrict__ windows,        // [B, L]
    const float* __restrict__ noise,          // [B, K]
    const float* __restrict__ init_centers,   // [K]
    const float* __restrict__ init_scales,    // [K]
    const float* __restrict__ init_weights,   // [K]
    const float* __restrict__ prior_p_param,  // [1]
    const float* __restrict__ mixw,           // [1, L]
    const float* __restrict__ blend,          // [1]
    float* __restrict__ out)                  // g [B,L,K] ++ p ++ a ++ b
{
    const int lane = threadIdx.x & 31;
    const int wid  = threadIdx.x >> 5;
    const int row  = blockIdx.x * RPB + wid;

    // ---- load row + per-position weights into registers (coalesced float4) ----
    const float4* __restrict__ xv = reinterpret_cast<const float4*>(windows + (size_t)row * Ln);
    const float4* __restrict__ mv = reinterpret_cast<const float4*>(mixw);

    float t[PPL], w[PPL];
    float s = 0.f;
#pragma unroll
    for (int j = 0; j < 8; j++) {
        float4 a = xv[lane + 32 * j];
        float4 m = mv[lane + 32 * j];
        t[4 * j + 0] = a.x; t[4 * j + 1] = a.y; t[4 * j + 2] = a.z; t[4 * j + 3] = a.w;
        s += (a.x + a.y) + (a.z + a.w);
        w[4 * j + 0] = __expf(m.x); w[4 * j + 1] = __expf(m.y);
        w[4 * j + 2] = __expf(m.z); w[4 * j + 3] = __expf(m.w);
    }
    const float mean = warp_sum(s) * (1.0f / Ln);

    float ss = 0.f;
#pragma unroll
    for (int i = 0; i < PPL; i++) {
        t[i] -= mean;
        ss = fmaf(t[i], t[i], ss);
    }
    const float var       = warp_sum(ss) * (1.0f / (Ln - 1));
    const float prior_var = var;
    const float stdv      = sqrtf(var);

    const float prior_p = rcpf(1.f + __expf(-prior_p_param[0]));
    const float blender = rcpf(1.f + __expf(-blend[0]));
    const float omb     = 1.f - blender;

    // ---- initial component params (every lane, all k; alpha = a - mean) ----
    float qa[Kc], qb[Kc], qc[Kc];           // logit quadratic: lm = (qa*t + qb)*t + qc
    float pk[Kc], al[Kc], bk[Kc];
#pragma unroll
    for (int k = 0; k < Kc; k++) {
        al[k] = (init_centers[k] + noise[(size_t)row * Kc + k] * 0.01f) * stdv;
        bk[k] = fabsf(init_scales[k]) * stdv;
        pk[k] = init_weights[k];
        float ib = rcpf(bk[k] + EPSF);
        qa[k] = NHALF_LOG2E * ib * ib;
        qb[k] = -2.f * qa[k] * al[k];
        qc[k] = fmaf(qa[k] * al[k], al[k], __log2f((pk[k] + EPSF) * ib));
    }

    float4* __restrict__ gout = reinterpret_cast<float4*>(out) + (size_t)row * Ln;

    // ---- EM iterations: no smem, no barriers; warp fully independent ----
#pragma unroll 1
    for (int it = 0; it < NIT; ++it) {
        const bool last = (it == NIT - 1);
        float acc[12];
#pragma unroll
        for (int m = 0; m < 12; m++) acc[m] = 0.f;

#pragma unroll
        for (int j = 0; j < 8; j++) {
#pragma unroll
            for (int c = 0; c < 4; c++) {
                const int i = 4 * j + c;
                const float ti = t[i];
                float e[Kc];
                float ssum = 0.f;
#pragma unroll
                for (int k = 0; k < Kc; k++) {
                    float lm = fmaf(fmaf(qa[k], ti, qb[k]), ti, qc[k]);
                    e[k] = ex2f(lm);
                    ssum += e[k];
                }
                const float rs = rcpf(ssum);
                if (last) {
                    gout[(lane + 32 * j) * 4 + c] =
                        make_float4(e[0] * rs, e[1] * rs, e[2] * rs, e[3] * rs);
                }
                const float ws = w[i] * rs;
#pragma unroll
                for (int k = 0; k < Kc; k++) {
                    float f  = e[k] * ws;
                    float ft = f * ti;
                    acc[k]     += f;
                    acc[4 + k] += ft;
                    acc[8 + k]  = fmaf(ft, ti, acc[8 + k]);
                }
            }
        }

        // ---- butterfly reduce 12 moments across the warp (all lanes get sums) ----
#pragma unroll
        for (int m = 0; m < 12; m++) acc[m] = warp_sum(acc[m]);

        // ---- m-step (redundant on every lane) ----
        float psum = 0.f;
#pragma unroll
        for (int k = 0; k < Kc; k++) {
            float sg = fmaxf(acc[k], EPSF);
            pk[k] = sg + prior_p;
            psum += pk[k];
        }
        const float rp = rcpf(psum);
#pragma unroll
        for (int k = 0; k < Kc; k++) {
            float S0 = acc[k], S1 = acc[4 + k], S2 = acc[8 + k];
            float sg  = fmaxf(S0, EPSF);
            float rsg = rcpf(sg);
            pk[k] *= rp;
            float a_  = blender * S1 * rsg;                          // a - mean
            float dv  = fmaf(a_, fmaf(a_, S0, -2.f * S1), S2) * rsg; // weighted var
            float bb  = sqrtf(fmaf(dv, blender, fmaf(prior_var, omb, EPSF)));
            float ib  = rcpf(bb + EPSF);
            al[k] = a_;
            bk[k] = bb;
            qa[k] = NHALF_LOG2E * ib * ib;
            qb[k] = -2.f * qa[k] * a_;
            qc[k] = fmaf(qa[k] * a_, a_, __log2f((pk[k] + EPSF) * ib));
        }
    }

    // ---- tail outputs: p, a, b ([B,K] each, after g) ----
    if (lane < Kc) {
        size_t base = (size_t)Bn * Ln * Kc;
        out[base + (size_t)row * Kc + lane]                       = pk[lane];
        out[base + (size_t)Bn * Kc + (size_t)row * Kc + lane]     = al[lane] + mean;
        out[base + 2 * (size_t)Bn * Kc + (size_t)row * Kc + lane] = bk[lane];
    }
}

extern "C" void kernel_launch(void* const* d_in, const int* in_sizes, int n_in,
                              void* d_out, int out_size) {
    (void)in_sizes; (void)n_in; (void)out_size;
    em_kernel<<<Bn / RPB, TPB>>>((const float*)d_in[0], (const float*)d_in[1],
                                 (const float*)d_in[2], (const float*)d_in[3],
                                 (const float*)d_in[4], (const float*)d_in[5],
                                 (const float*)d_in[6], (const float*)d_in[7],
                                 (float*)d_out);
}

// round 4
// speedup vs baseline: 2.3877x; 1.2372x over previous
#include <cuda_runtime.h>
#include <math.h>

#define EPSF 1e-8f
#define NHALF_LOG2E (-0.72134752044448170f)   // -0.5 * log2(e)

constexpr int Bn  = 4096;
constexpr int Ln  = 1024;
constexpr int Kc  = 4;
constexpr int NIT = 5;
constexpr int TPB = 256;
constexpr int RPB = TPB / 32;   // 8 rows (warps) per CTA
constexpr int NP  = 16;         // packed position-pairs per lane (32 positions)

using u64 = unsigned long long;

__device__ __forceinline__ float ex2f(float x){ float r; asm("ex2.approx.ftz.f32 %0, %1;":"=f"(r):"f"(x)); return r; }
__device__ __forceinline__ float rcpf(float x){ float r; asm("rcp.approx.ftz.f32 %0, %1;":"=f"(r):"f"(x)); return r; }

__device__ __forceinline__ u64 pk2(float lo, float hi){ u64 r; asm("mov.b64 %0, {%1, %2};":"=l"(r):"f"(lo),"f"(hi)); return r; }
__device__ __forceinline__ void up2(u64 v, float& lo, float& hi){ asm("mov.b64 {%0, %1}, %2;":"=f"(lo),"=f"(hi):"l"(v)); }
__device__ __forceinline__ u64 fma2(u64 a, u64 b, u64 c){ u64 d; asm("fma.rn.f32x2 %0, %1, %2, %3;":"=l"(d):"l"(a),"l"(b),"l"(c)); return d; }
__device__ __forceinline__ u64 add2(u64 a, u64 b){ u64 d; asm("add.rn.f32x2 %0, %1, %2;":"=l"(d):"l"(a),"l"(b)); return d; }
__device__ __forceinline__ u64 mul2(u64 a, u64 b){ u64 d; asm("mul.rn.f32x2 %0, %1, %2;":"=l"(d):"l"(a),"l"(b)); return d; }

__device__ __forceinline__ float warp_sum(float v){
#pragma unroll
    for (int o = 16; o; o >>= 1) v += __shfl_xor_sync(0xffffffffu, v, o);
    return v;
}
// reduce packed accumulator: add halves, then across warp
__device__ __forceinline__ float rsum2(u64 v){
    float a, b; up2(v, a, b);
    return warp_sum(a + b);
}

// Build packed broadcast quadratic-coefficient deltas (k=1..3 minus k=0)
// from per-lane (k = lane&3) scalar coefficients.
__device__ __forceinline__ void make_deltas(float qa, float qb, float qc,
                                            u64* dqa, u64* dqb, u64* dqc) {
    const unsigned F = 0xffffffffu;
    float a0 = __shfl_sync(F, qa, 0), a1 = __shfl_sync(F, qa, 1),
          a2 = __shfl_sync(F, qa, 2), a3 = __shfl_sync(F, qa, 3);
    float b0 = __shfl_sync(F, qb, 0), b1 = __shfl_sync(F, qb, 1),
          b2 = __shfl_sync(F, qb, 2), b3 = __shfl_sync(F, qb, 3);
    float c0 = __shfl_sync(F, qc, 0), c1 = __shfl_sync(F, qc, 1),
          c2 = __shfl_sync(F, qc, 2), c3 = __shfl_sync(F, qc, 3);
    float da1 = a1 - a0, da2 = a2 - a0, da3 = a3 - a0;
    float db1 = b1 - b0, db2 = b2 - b0, db3 = b3 - b0;
    float dc1 = c1 - c0, dc2 = c2 - c0, dc3 = c3 - c0;
    dqa[0] = pk2(da1, da1); dqa[1] = pk2(da2, da2); dqa[2] = pk2(da3, da3);
    dqb[0] = pk2(db1, db1); dqb[1] = pk2(db2, db2); dqb[2] = pk2(db3, db3);
    dqc[0] = pk2(dc1, dc1); dqc[1] = pk2(dc2, dc2); dqc[2] = pk2(dc3, dc3);
}

__global__ __launch_bounds__(TPB, 2) void em_kernel(
    const float* __restrict__ windows,        // [B, L]
    const float* __restrict__ noise,          // [B, K]
    const float* __restrict__ init_centers,   // [K]
    const float* __restrict__ init_scales,    // [K]
    const float* __restrict__ init_weights,   // [K]
    const float* __restrict__ prior_p_param,  // [1]
    const float* __restrict__ mixw,           // [1, L]
    const float* __restrict__ blend,          // [1]
    float* __restrict__ out)                  // g [B,L,K] ++ p ++ a ++ b
{
    __shared__ u64 wsh[NP][32];               // exp(mixw), pair-major, same for all rows

    const int lane = threadIdx.x & 31;
    const int wid  = threadIdx.x >> 5;
    const int row  = blockIdx.x * RPB + wid;

    // ---- stage per-position weights in smem (identical across rows/CTAs) ----
    {
        float4 m = reinterpret_cast<const float4*>(mixw)[lane + 32 * wid];
        wsh[2 * wid][lane]     = pk2(__expf(m.x), __expf(m.y));
        wsh[2 * wid + 1][lane] = pk2(__expf(m.z), __expf(m.w));
    }
    __syncthreads();

    // ---- load row into packed pairs; row mean ----
    const float4* __restrict__ xv = reinterpret_cast<const float4*>(windows + (size_t)row * Ln);
    u64 tp[NP];
    float s = 0.f;
#pragma unroll
    for (int j = 0; j < 8; j++) {
        float4 a = xv[lane + 32 * j];
        tp[2 * j]     = pk2(a.x, a.y);
        tp[2 * j + 1] = pk2(a.z, a.w);
        s += (a.x + a.y) + (a.z + a.w);
    }
    const float mean = warp_sum(s) * (1.0f / Ln);

    // ---- center (packed) + row var (ddof=1) ----
    const u64 nm2 = pk2(-mean, -mean);
    u64 ssp = 0ull;
#pragma unroll
    for (int p = 0; p < NP; p++) {
        tp[p] = add2(tp[p], nm2);
        ssp   = fma2(tp[p], tp[p], ssp);
    }
    const float var       = rsum2(ssp) * (1.0f / (Ln - 1));
    const float prior_var = var;
    const float stdv      = sqrtf(var);

    // ---- constant totals: W0=Σw, W1=Σw·t, W2=Σw·t² ----
    u64 W0p = 0ull, W1p = 0ull, W2p = 0ull;
#pragma unroll
    for (int p = 0; p < NP; p++) {
        u64 w2 = wsh[p][lane];
        W0p = add2(W0p, w2);
        u64 wt = mul2(w2, tp[p]);
        W1p = add2(W1p, wt);
        W2p = fma2(wt, tp[p], W2p);
    }
    const float W0 = rsum2(W0p), W1 = rsum2(W1p), W2 = rsum2(W2p);

    const float prior_p = rcpf(1.f + __expf(-prior_p_param[0]));
    const float blender = rcpf(1.f + __expf(-blend[0]));
    const float omb     = 1.f - blender;

    // ---- initial params: lane handles k = lane&3 ----
    const int k = lane & 3;
    float al_ = (init_centers[k] + noise[(size_t)row * Kc + k] * 0.01f) * stdv;
    float bb  = fabsf(init_scales[k]) * stdv;
    float pkn = init_weights[k];
    float ib  = rcpf(bb + EPSF);
    float qa  = NHALF_LOG2E * ib * ib;
    float qb  = -2.f * qa * al_;
    float qc  = fmaf(qa * al_, al_, __log2f((pkn + EPSF) * ib));

    u64 dqa[3], dqb[3], dqc[3];
    make_deltas(qa, qb, qc, dqa, dqb, dqc);

    const u64 one2 = pk2(1.f, 1.f);
    float4* __restrict__ gout = reinterpret_cast<float4*>(out) + (size_t)row * Ln;

    // ---- EM iterations ----
#pragma unroll 1
    for (int it = 0; it < NIT; ++it) {
        const bool last = (it == NIT - 1);
        u64 A0[3] = {0ull, 0ull, 0ull};
        u64 A1[3] = {0ull, 0ull, 0ull};
        u64 A2[3] = {0ull, 0ull, 0ull};

#pragma unroll
        for (int p = 0; p < NP; p++) {
            const u64 tpp = tp[p];
            // relative logits (log2 domain) vs component 0
            u64 d1 = fma2(fma2(dqa[0], tpp, dqb[0]), tpp, dqc[0]);
            u64 d2 = fma2(fma2(dqa[1], tpp, dqb[1]), tpp, dqc[1]);
            u64 d3 = fma2(fma2(dqa[2], tpp, dqb[2]), tpp, dqc[2]);
            float d1l, d1h, d2l, d2h, d3l, d3h;
            up2(d1, d1l, d1h); up2(d2, d2l, d2h); up2(d3, d3l, d3h);
            u64 e1 = pk2(ex2f(d1l), ex2f(d1h));
            u64 e2 = pk2(ex2f(d2l), ex2f(d2h));
            u64 e3 = pk2(ex2f(d3l), ex2f(d3h));
            u64 sm2 = add2(add2(e1, e2), add2(e3, one2));
            float sl, sh; up2(sm2, sl, sh);
            u64 rs2 = pk2(rcpf(sl), rcpf(sh));
            u64 w2  = wsh[p][lane];
            u64 ws2 = mul2(w2, rs2);

            if (last) {
                u64 g1 = mul2(e1, rs2), g2 = mul2(e2, rs2), g3 = mul2(e3, rs2);
                float rl, rh, g1l, g1h, g2l, g2h, g3l, g3h;
                up2(rs2, rl, rh); up2(g1, g1l, g1h); up2(g2, g2l, g2h); up2(g3, g3l, g3h);
                const int j = p >> 1, h = p & 1;
                const int pos = (lane + 32 * j) * 4 + 2 * h;
                gout[pos]     = make_float4(rl, g1l, g2l, g3l);
                gout[pos + 1] = make_float4(rh, g1h, g2h, g3h);
            }

            // f_k = g_k * w  (k=0: e0=1 so f0 = ws)
            u64 f0 = ws2;
            u64 f1 = mul2(e1, ws2);
            u64 f2 = mul2(e2, ws2);
            u64 t0 = mul2(f0, tpp), t1 = mul2(f1, tpp), t2 = mul2(f2, tpp);
            A0[0] = add2(A0[0], f0); A0[1] = add2(A0[1], f1); A0[2] = add2(A0[2], f2);
            A1[0] = add2(A1[0], t0); A1[1] = add2(A1[1], t1); A1[2] = add2(A1[2], t2);
            A2[0] = fma2(t0, tpp, A2[0]); A2[1] = fma2(t1, tpp, A2[1]); A2[2] = fma2(t2, tpp, A2[2]);
        }

        // ---- reduce 9 moments (k=3 derived from conserved totals) ----
        float S00 = rsum2(A0[0]), S01 = rsum2(A0[1]), S02 = rsum2(A0[2]);
        float S10 = rsum2(A1[0]), S11 = rsum2(A1[1]), S12 = rsum2(A1[2]);
        float S20 = rsum2(A2[0]), S21 = rsum2(A2[1]), S22 = rsum2(A2[2]);

        float S0k = (k == 0) ? S00 : (k == 1) ? S01 : (k == 2) ? S02 : (W0 - S00 - S01 - S02);
        float S1k = (k == 0) ? S10 : (k == 1) ? S11 : (k == 2) ? S12 : (W1 - S10 - S11 - S12);
        float S2k = (k == 0) ? S20 : (k == 1) ? S21 : (k == 2) ? S22 : (W2 - S20 - S21 - S22);

        // ---- m-step: lane computes its k ----
        float sg = fmaxf(S0k, EPSF);
        float pv = sg + prior_p;
        float psum = pv;
        psum += __shfl_xor_sync(0xffffffffu, psum, 1);
        psum += __shfl_xor_sync(0xffffffffu, psum, 2);
        pkn = pv * rcpf(psum);
        float rsg = rcpf(sg);
        al_ = blender * S1k * rsg;                                  // a - mean
        float dv = fmaf(al_, fmaf(al_, S0k, -2.f * S1k), S2k) * rsg;
        bb = sqrtf(fmaf(dv, blender, fmaf(prior_var, omb, EPSF)));
        ib = rcpf(bb + EPSF);
        qa = NHALF_LOG2E * ib * ib;
        qb = -2.f * qa * al_;
        qc = fmaf(qa * al_, al_, __log2f((pkn + EPSF) * ib));
        make_deltas(qa, qb, qc, dqa, dqb, dqc);
    }

    // ---- tail outputs: p, a, b (lane < 4 holds k = lane) ----
    if (lane < Kc) {
        size_t base = (size_t)Bn * Ln * Kc;
        out[base + (size_t)row * Kc + lane]                       = pkn;
        out[base + (size_t)Bn * Kc + (size_t)row * Kc + lane]     = al_ + mean;
        out[base + 2 * (size_t)Bn * Kc + (size_t)row * Kc + lane] = bb;
    }
}

extern "C" void kernel_launch(void* const* d_in, const int* in_sizes, int n_in,
                              void* d_out, int out_size) {
    (void)in_sizes; (void)n_in; (void)out_size;
    em_kernel<<<Bn / RPB, TPB>>>((const float*)d_in[0], (const float*)d_in[1],
                                 (const float*)d_in[2], (const float*)d_in[3],
                                 (const float*)d_in[4], (const float*)d_in[5],
                                 (const float*)d_in[6], (const float*)d_in[7],
                                 (float*)d_out);
}